// round 3
// baseline (speedup 1.0000x reference)
#include <cuda_runtime.h>
#include <math.h>
#include <stdint.h>

#define VOCAB 32000
#define EMB 32
#define REC 16
#define SEQ 256
#define BATCH 32
#define NROWS (SEQ*BATCH)      // 8192
#define LOG2E 1.4426950408889634f
#define LN2   0.6931471805599453f

// ---- scratch (static device globals; no allocation allowed) ----
__device__ float g_Vt[REC*VOCAB];       // V^T, scaled by log2e, tf32-rounded bit patterns
__device__ float g_ih[BATCH*SEQ*REC];   // x@U^T + b1 + b2, layout [b][t][j]
__device__ float g_h[SEQ*BATCH*REC];    // hidden (pre-step state), tf32-rounded, [s][b][j]
__device__ float g_sums[NROWS];         // sum(2^c) per row
__device__ float g_m[NROWS];            // log2(sum)*ln2 per row

// ---- helpers ----
__device__ __forceinline__ uint32_t f2tf32(float x) {
    uint32_t u;
    asm("cvt.rna.tf32.f32 %0, %1;" : "=r"(u) : "f"(x));
    return u;
}
__device__ __forceinline__ float ex2f(float x) {
    float y;
    asm("ex2.approx.f32 %0, %1;" : "=f"(y) : "f"(x));
    return y;
}
__device__ __forceinline__ void mma_tf32(float c[4], const uint32_t a[4], const uint32_t b[2]) {
    asm("mma.sync.aligned.m16n8k8.row.col.f32.tf32.tf32.f32 "
        "{%0,%1,%2,%3},{%4,%5,%6,%7},{%8,%9},{%0,%1,%2,%3};"
        : "+f"(c[0]), "+f"(c[1]), "+f"(c[2]), "+f"(c[3])
        : "r"(a[0]), "r"(a[1]), "r"(a[2]), "r"(a[3]), "r"(b[0]), "r"(b[1]));
}

// ---- small kernels ----
__global__ void k_zero() {
    g_sums[blockIdx.x * blockDim.x + threadIdx.x] = 0.f;
}

// V^T with log2e folded in, tf32-rounded
__global__ void k_transV(const float* __restrict__ V) {
    int v = blockIdx.x * blockDim.x + threadIdx.x;   // 0..31999
    const float4* v4 = (const float4*)(V + v * REC);
    float4 a0 = v4[0], a1 = v4[1], a2 = v4[2], a3 = v4[3];
    float vals[REC] = {a0.x,a0.y,a0.z,a0.w, a1.x,a1.y,a1.z,a1.w,
                       a2.x,a2.y,a2.z,a2.w, a3.x,a3.y,a3.z,a3.w};
#pragma unroll
    for (int e = 0; e < REC; e++)
        g_Vt[e * VOCAB + v] = __uint_as_float(f2tf32(vals[e] * LOG2E));
}

// ih[b][t][j] = emb[tok[t,b]] . U[j] + b1[j] + b2[j]
__global__ void k_ih(const int* __restrict__ idx, const float* __restrict__ emb,
                     const float* __restrict__ U, const float* __restrict__ b1,
                     const float* __restrict__ b2) {
    int i = blockIdx.x * blockDim.x + threadIdx.x;   // 0..131071
    int row = i >> 4;        // t*BATCH + b
    int j   = i & 15;
    int t = row >> 5, b = row & 31;
    int tok = idx[row];
    const float4* x4 = (const float4*)(emb + (size_t)tok * EMB);
    const float4* u4 = (const float4*)(U + j * EMB);
    float acc = b1[j] + b2[j];
#pragma unroll
    for (int q = 0; q < 8; q++) {
        float4 x = x4[q], u = u4[q];
        acc = fmaf(x.x, u.x, acc); acc = fmaf(x.y, u.y, acc);
        acc = fmaf(x.z, u.z, acc); acc = fmaf(x.w, u.w, acc);
    }
    g_ih[b * (SEQ * REC) + t * REC + j] = acc;
}

// recurrence: 1 warp per batch, 2 lanes per recurrent unit
__global__ void k_rnn(const float* __restrict__ W, const float* __restrict__ h0) {
    __shared__ float ihs[SEQ * REC];   // 16 KB
    __shared__ float hsm[REC];
    int b = blockIdx.x;
    int lane = threadIdx.x;

#pragma unroll 8
    for (int i = lane; i < SEQ * REC; i += 32)
        ihs[i] = g_ih[b * (SEQ * REC) + i];

    int j = lane >> 1;
    int half = lane & 1;
    float Wr[8];
#pragma unroll
    for (int k = 0; k < 8; k++) Wr[k] = W[j * REC + half * 8 + k];

    if (lane < REC) hsm[lane] = h0[lane];
    __syncwarp();

    for (int t = 0; t < SEQ; t++) {
        float h = hsm[j];
        if (!half) g_h[(t * BATCH + b) * REC + j] = __uint_as_float(f2tf32(h));
        if (t == SEQ - 1) break;

        const float* hp = &hsm[half * 8];
        float a0 = Wr[0]*hp[0], a1 = Wr[1]*hp[1];
        a0 = fmaf(Wr[2], hp[2], a0); a1 = fmaf(Wr[3], hp[3], a1);
        a0 = fmaf(Wr[4], hp[4], a0); a1 = fmaf(Wr[5], hp[5], a1);
        a0 = fmaf(Wr[6], hp[6], a0); a1 = fmaf(Wr[7], hp[7], a1);
        float acc = a0 + a1;
        acc += __shfl_xor_sync(0xffffffffu, acc, 1);
        float hn = tanhf(ihs[t * REC + j] + acc);
        __syncwarp();
        if (!half) hsm[j] = hn;
        __syncwarp();
    }
}

// ---- pass kernels: 256 threads (8 warps), warp owns 32 vocab, CTA covers 256 vocab, 8 s-steps ----
#define S_PER_CTA 8

// compute C[16] for one rowgroup; a-regs from hs (stride 17), B regs preloaded
__device__ __forceinline__ void compute_rowgroup(
    float C[16], const float* hs, const uint32_t B[4][2][2], int rg, int g, int t)
{
#pragma unroll
    for (int q = 0; q < 16; q++) C[q] = 0.f;
    uint32_t A[2][4];
#pragma unroll
    for (int ks = 0; ks < 2; ks++) {
        int r0 = (rg * 16 + g) * 17;
        int r1 = (rg * 16 + g + 8) * 17;
        int c0 = t + ks * 8;
        A[ks][0] = __float_as_uint(hs[r0 + c0]);
        A[ks][1] = __float_as_uint(hs[r1 + c0]);
        A[ks][2] = __float_as_uint(hs[r0 + c0 + 4]);
        A[ks][3] = __float_as_uint(hs[r1 + c0 + 4]);
    }
#pragma unroll
    for (int i = 0; i < 4; i++) {
        mma_tf32(C + i * 4, A[0], B[i][0]);
        mma_tf32(C + i * 4, A[1], B[i][1]);
    }
}

__global__ void __launch_bounds__(256) k_pass1() {
    __shared__ float vt_s[REC * 256];       // 16 KB V tile (tf32 bits)
    __shared__ float hs[BATCH * 17];        // padded hidden slab
    __shared__ float rs[BATCH];
    int tid = threadIdx.x;
    int warp = tid >> 5, lane = tid & 31;
    int g = lane >> 2, t = lane & 3;
    int vbase_cta = blockIdx.x * 256;

    for (int i = tid; i < REC * 256; i += 256)
        vt_s[i] = g_Vt[(i >> 8) * VOCAB + vbase_cta + (i & 255)];
    __syncthreads();

    uint32_t B[4][2][2];
#pragma unroll
    for (int i = 0; i < 4; i++)
#pragma unroll
        for (int ks = 0; ks < 2; ks++)
#pragma unroll
            for (int j = 0; j < 2; j++)
                B[i][ks][j] = __float_as_uint(
                    vt_s[(t + 4 * j + 8 * ks) * 256 + warp * 32 + g * 4 + i]);

    for (int si = 0; si < S_PER_CTA; si++) {
        int s = blockIdx.y * S_PER_CTA + si;
        for (int i = tid; i < BATCH * REC; i += 256)
            hs[(i >> 4) * 17 + (i & 15)] = g_h[s * (BATCH * REC) + i];
        if (tid < BATCH) rs[tid] = 0.f;
        __syncthreads();

#pragma unroll
        for (int rg = 0; rg < 2; rg++) {
            float C[16];
            compute_rowgroup(C, hs, B, rg, g, t);
            float p0 = 0.f, p1 = 0.f;
#pragma unroll
            for (int i = 0; i < 4; i++) {
                p0 += ex2f(C[i * 4 + 0]) + ex2f(C[i * 4 + 1]);
                p1 += ex2f(C[i * 4 + 2]) + ex2f(C[i * 4 + 3]);
            }
            p0 += __shfl_xor_sync(0xffffffffu, p0, 1);
            p0 += __shfl_xor_sync(0xffffffffu, p0, 2);
            p1 += __shfl_xor_sync(0xffffffffu, p1, 1);
            p1 += __shfl_xor_sync(0xffffffffu, p1, 2);
            if (t == 0) {
                atomicAdd(&rs[rg * 16 + g], p0);
                atomicAdd(&rs[rg * 16 + g + 8], p1);
            }
        }
        __syncthreads();
        if (tid < BATCH) atomicAdd(&g_sums[s * BATCH + tid], rs[tid]);
        __syncthreads();
    }
}

__global__ void k_lse() {
    int i = blockIdx.x * blockDim.x + threadIdx.x;
    g_m[i] = log2f(g_sums[i]) * LN2;
}

__global__ void __launch_bounds__(256) k_pass2(float* __restrict__ out) {
    __shared__ float vt_s[REC * 256];
    __shared__ float hs[BATCH * 17];
    __shared__ float ms[BATCH];
    int tid = threadIdx.x;
    int warp = tid >> 5, lane = tid & 31;
    int g = lane >> 2, t = lane & 3;
    int vbase_cta = blockIdx.x * 256;
    int vwarp = vbase_cta + warp * 32;

    for (int i = tid; i < REC * 256; i += 256)
        vt_s[i] = g_Vt[(i >> 8) * VOCAB + vbase_cta + (i & 255)];
    __syncthreads();

    uint32_t B[4][2][2];
#pragma unroll
    for (int i = 0; i < 4; i++)
#pragma unroll
        for (int ks = 0; ks < 2; ks++)
#pragma unroll
            for (int j = 0; j < 2; j++)
                B[i][ks][j] = __float_as_uint(
                    vt_s[(t + 4 * j + 8 * ks) * 256 + warp * 32 + g * 4 + i]);

    for (int si = 0; si < S_PER_CTA; si++) {
        int s = blockIdx.y * S_PER_CTA + si;
        for (int i = tid; i < BATCH * REC; i += 256)
            hs[(i >> 4) * 17 + (i & 15)] = g_h[s * (BATCH * REC) + i];
        if (tid < BATCH) ms[tid] = g_m[s * BATCH + tid];
        __syncthreads();

#pragma unroll
        for (int rg = 0; rg < 2; rg++) {
            float C[16];
            compute_rowgroup(C, hs, B, rg, g, t);
            float m0 = ms[rg * 16 + g];
            float m1 = ms[rg * 16 + g + 8];
            size_t row0 = (size_t)(s * BATCH + rg * 16 + g) * VOCAB;
            size_t row1 = row0 + (size_t)8 * VOCAB;
            int v0 = vwarp + 8 * t;
            float4 q;
            q.x = fmaf(C[0],  LN2, -m0); q.y = fmaf(C[4],  LN2, -m0);
            q.z = fmaf(C[8],  LN2, -m0); q.w = fmaf(C[12], LN2, -m0);
            *(float4*)(out + row0 + v0) = q;
            q.x = fmaf(C[1],  LN2, -m0); q.y = fmaf(C[5],  LN2, -m0);
            q.z = fmaf(C[9],  LN2, -m0); q.w = fmaf(C[13], LN2, -m0);
            *(float4*)(out + row0 + v0 + 4) = q;
            q.x = fmaf(C[2],  LN2, -m1); q.y = fmaf(C[6],  LN2, -m1);
            q.z = fmaf(C[10], LN2, -m1); q.w = fmaf(C[14], LN2, -m1);
            *(float4*)(out + row1 + v0) = q;
            q.x = fmaf(C[3],  LN2, -m1); q.y = fmaf(C[7],  LN2, -m1);
            q.z = fmaf(C[11], LN2, -m1); q.w = fmaf(C[15], LN2, -m1);
            *(float4*)(out + row1 + v0 + 4) = q;
        }
        __syncthreads();
    }
}

extern "C" void kernel_launch(void* const* d_in, const int* in_sizes, int n_in,
                              void* d_out, int out_size) {
    const int*   input_batch = (const int*)  d_in[0];
    const float* embedding   = (const float*)d_in[1];
    const float* U           = (const float*)d_in[2];
    const float* W           = (const float*)d_in[3];
    const float* V           = (const float*)d_in[4];
    const float* b1          = (const float*)d_in[5];
    const float* b2          = (const float*)d_in[6];
    const float* h0          = (const float*)d_in[7];
    float* out = (float*)d_out;

    k_zero  <<<NROWS / 256, 256>>>();
    k_transV<<<VOCAB / 256, 256>>>(V);
    k_ih    <<<(NROWS * REC) / 256, 256>>>(input_batch, embedding, U, b1, b2);
    k_rnn   <<<BATCH, 32>>>(W, h0);
    k_pass1 <<<dim3(VOCAB / 256, SEQ / S_PER_CTA), 256>>>();
    k_lse   <<<NROWS / 256, 256>>>();
    k_pass2 <<<dim3(VOCAB / 256, SEQ / S_PER_CTA), 256>>>(out);
}

// round 5
// speedup vs baseline: 1.3281x; 1.3281x over previous
#include <cuda_runtime.h>
#include <math.h>
#include <stdint.h>

#define VOCAB 32000
#define EMB 32
#define REC 16
#define SEQ 256
#define BATCH 32
#define NROWS (SEQ*BATCH)      // 8192
#define LOG2E 1.4426950408889634f
#define LN2   0.6931471805599453f
#define TP 160                 // threads per pass CTA (5 warps)
#define VCH 640                // vocab per pass CTA
#define S_PER_CTA 8

// ---- scratch (static device globals) ----
__device__ float  g_Vt[REC*VOCAB];      // V^T * log2e, [e][v]
__device__ float  g_ih[BATCH*SEQ*REC];  // (x@U^T + b1 + b2) * 2*log2e, [b][t][j]
__device__ float4 g_hd4[SEQ*BATCH*8];   // hidden dup pairs: each row = 8 float4 = 16 (h,h)
__device__ float  g_sums[NROWS];        // sum(2^c) per row
__device__ float  g_m[NROWS];           // lse in nat units

// ---- helpers ----
__device__ __forceinline__ float ex2f(float x) {
    float y; asm("ex2.approx.f32 %0, %1;" : "=f"(y) : "f"(x)); return y;
}
__device__ __forceinline__ float rcpf(float x) {
    float y; asm("rcp.approx.f32 %0, %1;" : "=f"(y) : "f"(x)); return y;
}
__device__ __forceinline__ float2 ffma2(float2 a, float2 b, float2 c) {
    float2 d;
    asm("fma.rn.f32x2 %0, %1, %2, %3;"
        : "=l"(reinterpret_cast<unsigned long long&>(d))
        : "l"(reinterpret_cast<unsigned long long&>(a)),
          "l"(reinterpret_cast<unsigned long long&>(b)),
          "l"(reinterpret_cast<unsigned long long&>(c)));
    return d;
}

// ---- small kernels ----
__global__ void k_zero() { g_sums[blockIdx.x * blockDim.x + threadIdx.x] = 0.f; }

__global__ void k_transV(const float* __restrict__ V) {
    int v = blockIdx.x * blockDim.x + threadIdx.x;
    const float4* v4 = (const float4*)(V + v * REC);
    float4 a0 = v4[0], a1 = v4[1], a2 = v4[2], a3 = v4[3];
    float vals[REC] = {a0.x,a0.y,a0.z,a0.w, a1.x,a1.y,a1.z,a1.w,
                       a2.x,a2.y,a2.z,a2.w, a3.x,a3.y,a3.z,a3.w};
#pragma unroll
    for (int e = 0; e < REC; e++) g_Vt[e * VOCAB + v] = vals[e] * LOG2E;
}

// ih[b][t][j] = (emb[tok].U[j] + b1[j] + b2[j]) * 2*log2e
__global__ void k_ih(const int* __restrict__ idx, const float* __restrict__ emb,
                     const float* __restrict__ U, const float* __restrict__ b1,
                     const float* __restrict__ b2) {
    int i = blockIdx.x * blockDim.x + threadIdx.x;
    int row = i >> 4;          // t*BATCH + b
    int j   = i & 15;
    int t = row >> 5, b = row & 31;
    int tok = idx[row];
    const float4* x4 = (const float4*)(emb + (size_t)tok * EMB);
    const float4* u4 = (const float4*)(U + j * EMB);
    float acc = b1[j] + b2[j];
#pragma unroll
    for (int q = 0; q < 8; q++) {
        float4 x = x4[q], u = u4[q];
        acc = fmaf(x.x, u.x, acc); acc = fmaf(x.y, u.y, acc);
        acc = fmaf(x.z, u.z, acc); acc = fmaf(x.w, u.w, acc);
    }
    g_ih[b * (SEQ * REC) + t * REC + j] = acc * (2.0f * LOG2E);
}

// recurrence: 1 warp per batch, 2 lanes per unit, double-buffered h in smem
__global__ void k_rnn(const float* __restrict__ W, const float* __restrict__ h0) {
    __shared__ float ihs[SEQ * REC];
    __shared__ float hsm[2][REC];
    int b = blockIdx.x;
    int lane = threadIdx.x;

#pragma unroll 8
    for (int i = lane; i < SEQ * REC; i += 32)
        ihs[i] = g_ih[b * (SEQ * REC) + i];

    int j = lane >> 1;
    int half = lane & 1;
    float Wr[8];
#pragma unroll
    for (int k = 0; k < 8; k++) Wr[k] = W[j * REC + half * 8 + k];

    if (lane < REC) hsm[0][lane] = h0[lane];
    __syncwarp();

    int cur = 0;
    float* hrow = (float*)&g_hd4[b * 8];   // 8 float4 per (s,b) row
    for (int t = 0; t < SEQ; t++) {
        // store h_t (pre-update state) as duplicated pair
        if (!half) {
            float h = hsm[cur][j];
            ((float2*)hrow)[j] = make_float2(h, h);
        }
        if (t == SEQ - 1) break;
        hrow += BATCH * 32;                // next s: BATCH rows * 32 floats

        const float* hp = &hsm[cur][half * 8];
        float a0 = Wr[0]*hp[0], a1 = Wr[1]*hp[1];
        a0 = fmaf(Wr[2], hp[2], a0); a1 = fmaf(Wr[3], hp[3], a1);
        a0 = fmaf(Wr[4], hp[4], a0); a1 = fmaf(Wr[5], hp[5], a1);
        a0 = fmaf(Wr[6], hp[6], a0); a1 = fmaf(Wr[7], hp[7], a1);
        float acc = a0 + a1;
        acc += __shfl_xor_sync(0xffffffffu, acc, 1);
        // z = 2*log2e*(ih + acc); ihs already pre-scaled by 2*log2e
        float z = fmaf(acc, 2.0f * LOG2E, ihs[t * REC + j]);
        float e = ex2f(z);                              // e^{2x}
        float hn = fmaf(-2.0f, rcpf(1.0f + e), 1.0f);   // tanh(x)
        if (!half) hsm[cur ^ 1][j] = hn;
        __syncwarp();
        cur ^= 1;
    }
}

// ---- pass kernels: 160 threads, 4 vocab/thread (2 float2), 8 s-steps per CTA ----
__global__ void __launch_bounds__(TP) k_pass1() {
    int tid = threadIdx.x;
    int v0 = blockIdx.x * VCH + 2 * tid;   // [base, base+320)
    int v1 = v0 + 320;

    float2 Va[REC], Vb[REC];
#pragma unroll
    for (int e = 0; e < REC; e++) {
        Va[e] = *(const float2*)&g_Vt[e * VOCAB + v0];
        Vb[e] = *(const float2*)&g_Vt[e * VOCAB + v1];
    }

    __shared__ float4 hs4[BATCH * 8];
    __shared__ float  rs[BATCH];

    for (int si = 0; si < S_PER_CTA; si++) {
        int s = blockIdx.y * S_PER_CTA + si;
        for (int i = tid; i < BATCH * 8; i += TP) hs4[i] = g_hd4[s * (BATCH * 8) + i];
        if (tid < BATCH) rs[tid] = 0.f;
        __syncthreads();

#pragma unroll 4
        for (int b = 0; b < BATCH; b++) {
            const float4* hp = &hs4[b * 8];
            float2 a0 = make_float2(0.f, 0.f), a1 = make_float2(0.f, 0.f);
#pragma unroll
            for (int q = 0; q < 8; q++) {
                float4 hq = hp[q];
                float2 hlo = make_float2(hq.x, hq.y);
                float2 hhi = make_float2(hq.z, hq.w);
                a0 = ffma2(Va[2*q],   hlo, a0); a1 = ffma2(Vb[2*q],   hlo, a1);
                a0 = ffma2(Va[2*q+1], hhi, a0); a1 = ffma2(Vb[2*q+1], hhi, a1);
            }
            float p = (ex2f(a0.x) + ex2f(a0.y)) + (ex2f(a1.x) + ex2f(a1.y));
#pragma unroll
            for (int o = 16; o > 0; o >>= 1) p += __shfl_xor_sync(0xffffffffu, p, o);
            if ((tid & 31) == 0) atomicAdd(&rs[b], p);
        }
        __syncthreads();
        if (tid < BATCH) atomicAdd(&g_sums[s * BATCH + tid], rs[tid]);
        __syncthreads();
    }
}

__global__ void k_lse() {
    int i = blockIdx.x * blockDim.x + threadIdx.x;
    g_m[i] = log2f(g_sums[i]) * LN2;
}

__global__ void __launch_bounds__(TP) k_pass2(float* __restrict__ out) {
    int tid = threadIdx.x;
    int v0 = blockIdx.x * VCH + 2 * tid;
    int v1 = v0 + 320;

    float2 Va[REC], Vb[REC];
#pragma unroll
    for (int e = 0; e < REC; e++) {
        Va[e] = *(const float2*)&g_Vt[e * VOCAB + v0];
        Vb[e] = *(const float2*)&g_Vt[e * VOCAB + v1];
    }

    __shared__ float4 hs4[BATCH * 8];
    __shared__ float  ms[BATCH];

    for (int si = 0; si < S_PER_CTA; si++) {
        int s = blockIdx.y * S_PER_CTA + si;
        for (int i = tid; i < BATCH * 8; i += TP) hs4[i] = g_hd4[s * (BATCH * 8) + i];
        if (tid < BATCH) ms[tid] = g_m[s * BATCH + tid];
        __syncthreads();

#pragma unroll 4
        for (int b = 0; b < BATCH; b++) {
            const float4* hp = &hs4[b * 8];
            float2 a0 = make_float2(0.f, 0.f), a1 = make_float2(0.f, 0.f);
#pragma unroll
            for (int q = 0; q < 8; q++) {
                float4 hq = hp[q];
                float2 hlo = make_float2(hq.x, hq.y);
                float2 hhi = make_float2(hq.z, hq.w);
                a0 = ffma2(Va[2*q],   hlo, a0); a1 = ffma2(Vb[2*q],   hlo, a1);
                a0 = ffma2(Va[2*q+1], hhi, a0); a1 = ffma2(Vb[2*q+1], hhi, a1);
            }
            float m = ms[b];
            size_t rowoff = (size_t)(s * BATCH + b) * VOCAB;
            float2 r0, r1;
            r0.x = fmaf(a0.x, LN2, -m); r0.y = fmaf(a0.y, LN2, -m);
            r1.x = fmaf(a1.x, LN2, -m); r1.y = fmaf(a1.y, LN2, -m);
            *(float2*)(out + rowoff + v0) = r0;
            *(float2*)(out + rowoff + v1) = r1;
        }
        __syncthreads();
    }
}

extern "C" void kernel_launch(void* const* d_in, const int* in_sizes, int n_in,
                              void* d_out, int out_size) {
    const int*   input_batch = (const int*)  d_in[0];
    const float* embedding   = (const float*)d_in[1];
    const float* U           = (const float*)d_in[2];
    const float* W           = (const float*)d_in[3];
    const float* V           = (const float*)d_in[4];
    const float* b1          = (const float*)d_in[5];
    const float* b2          = (const float*)d_in[6];
    const float* h0          = (const float*)d_in[7];
    float* out = (float*)d_out;

    k_zero  <<<NROWS / 256, 256>>>();
    k_transV<<<VOCAB / 256, 256>>>(V);
    k_ih    <<<(NROWS * REC) / 256, 256>>>(input_batch, embedding, U, b1, b2);
    k_rnn   <<<BATCH, 32>>>(W, h0);
    k_pass1 <<<dim3(VOCAB / VCH, SEQ / S_PER_CTA), TP>>>();
    k_lse   <<<NROWS / 256, 256>>>();
    k_pass2 <<<dim3(VOCAB / VCH, SEQ / S_PER_CTA), TP>>>(out);
}

// round 8
// speedup vs baseline: 1.5311x; 1.1528x over previous
#include <cuda_runtime.h>
#include <cuda_fp16.h>
#include <math.h>
#include <stdint.h>

#define VOCAB 32000
#define EMB 32
#define REC 16
#define SEQ 256
#define BATCH 32
#define NROWS (SEQ*BATCH)      // 8192
#define NPAIR (VOCAB/2)        // 16000 vocab pairs
#define LOG2E 1.4426950408889634f
#define LN2   0.6931471805599453f
#define TP 160                 // threads per pass CTA
#define VCH 640                // vocab per pass CTA (160 threads * 4)
#define S_PER_CTA 8

// ---- scratch (static device globals) ----
__device__ __half2 g_Vh[REC*NPAIR];     // packed (V[2p][e],V[2p+1][e])*log2e, [e][p]
__device__ float   g_ih[BATCH*SEQ*REC]; // (x@U^T + b1 + b2)*2*log2e, [b][t][j]
__device__ __half2 g_hh[NROWS*REC];     // hidden dup (h,h) fp16, [s][b][j]
__device__ float   g_sums[NROWS];       // sum(2^c) per row
__device__ float   g_m[NROWS];          // lse (nat units)

// ---- helpers ----
__device__ __forceinline__ float ex2f(float x) {
    float y; asm("ex2.approx.f32 %0, %1;" : "=f"(y) : "f"(x)); return y;
}
__device__ __forceinline__ float rcpf(float x) {
    float y; asm("rcp.approx.f32 %0, %1;" : "=f"(y) : "f"(x)); return y;
}

// ---- small kernels ----
__global__ void k_zero() { g_sums[blockIdx.x * blockDim.x + threadIdx.x] = 0.f; }

// pack V^T * log2e into half2 vocab pairs: g_Vh[e][p] = (V[2p][e], V[2p+1][e])
__global__ void k_transV(const float* __restrict__ V) {
    int p = blockIdx.x * blockDim.x + threadIdx.x;   // 0..15999
    const float4* a4 = (const float4*)(V + (size_t)(2*p)   * REC);
    const float4* b4 = (const float4*)(V + (size_t)(2*p+1) * REC);
    float av[REC], bv[REC];
#pragma unroll
    for (int q = 0; q < 4; q++) {
        float4 a = a4[q], b = b4[q];
        av[4*q]=a.x; av[4*q+1]=a.y; av[4*q+2]=a.z; av[4*q+3]=a.w;
        bv[4*q]=b.x; bv[4*q+1]=b.y; bv[4*q+2]=b.z; bv[4*q+3]=b.w;
    }
#pragma unroll
    for (int e = 0; e < REC; e++)
        g_Vh[e * NPAIR + p] = __floats2half2_rn(av[e] * LOG2E, bv[e] * LOG2E);
}

// ih[b][t][j] = (emb[tok].U[j] + b1[j] + b2[j]) * 2*log2e
__global__ void k_ih(const int* __restrict__ idx, const float* __restrict__ emb,
                     const float* __restrict__ U, const float* __restrict__ b1,
                     const float* __restrict__ b2) {
    int i = blockIdx.x * blockDim.x + threadIdx.x;
    int row = i >> 4;          // t*BATCH + b
    int j   = i & 15;
    int t = row >> 5, b = row & 31;
    int tok = idx[row];
    const float4* x4 = (const float4*)(emb + (size_t)tok * EMB);
    const float4* u4 = (const float4*)(U + j * EMB);
    float acc = b1[j] + b2[j];
#pragma unroll
    for (int q = 0; q < 8; q++) {
        float4 x = x4[q], u = u4[q];
        acc = fmaf(x.x, u.x, acc); acc = fmaf(x.y, u.y, acc);
        acc = fmaf(x.z, u.z, acc); acc = fmaf(x.w, u.w, acc);
    }
    g_ih[b * (SEQ * REC) + t * REC + j] = acc * (2.0f * LOG2E);
}

// recurrence: 1 warp per batch, 2 lanes per unit, double-buffered h in smem
__global__ void k_rnn(const float* __restrict__ W, const float* __restrict__ h0) {
    __shared__ float ihs[SEQ * REC];
    __shared__ float hsm[2][REC];
    int b = blockIdx.x;
    int lane = threadIdx.x;

#pragma unroll 8
    for (int i = lane; i < SEQ * REC; i += 32)
        ihs[i] = g_ih[b * (SEQ * REC) + i];

    int j = lane >> 1;
    int half = lane & 1;
    float Wr[8];
#pragma unroll
    for (int k = 0; k < 8; k++) Wr[k] = W[j * REC + half * 8 + k];

    if (lane < REC) hsm[0][lane] = h0[lane];
    __syncwarp();

    int cur = 0;
    __half2* hrow = &g_hh[b * REC];        // row (s=0,b)
    for (int t = 0; t < SEQ; t++) {
        if (!half) {
            float h = hsm[cur][j];
            hrow[j] = __half2half2(__float2half_rn(h));
        }
        if (t == SEQ - 1) break;
        hrow += BATCH * REC;               // next s

        const float* hp = &hsm[cur][half * 8];
        float a0 = Wr[0]*hp[0], a1 = Wr[1]*hp[1];
        a0 = fmaf(Wr[2], hp[2], a0); a1 = fmaf(Wr[3], hp[3], a1);
        a0 = fmaf(Wr[4], hp[4], a0); a1 = fmaf(Wr[5], hp[5], a1);
        a0 = fmaf(Wr[6], hp[6], a0); a1 = fmaf(Wr[7], hp[7], a1);
        float acc = a0 + a1;
        acc += __shfl_xor_sync(0xffffffffu, acc, 1);
        float z = fmaf(acc, 2.0f * LOG2E, ihs[t * REC + j]);  // 2*log2e*(ih+acc)
        float e = ex2f(z);
        float hn = fmaf(-2.0f, rcpf(1.0f + e), 1.0f);         // tanh
        if (!half) hsm[cur ^ 1][j] = hn;
        __syncwarp();
        cur ^= 1;
    }
}

// ---- pass kernels: 160 threads, 4 vocab/thread (2 half2 pairs), 8 s per CTA ----
// V regs: Vr[e][0..1] half2 -> 32 regs.  GEMM: 32 HFMA2 per b-iter (rt=2).
__global__ void __launch_bounds__(TP) k_pass1() {
    int tid = threadIdx.x;
    int p0 = (blockIdx.x * VCH) / 2 + 2 * tid;   // vocab pair idx

    __half2 Vr[REC][2];
#pragma unroll
    for (int e = 0; e < REC; e++) {
        uint2 u = *(const uint2*)&g_Vh[e * NPAIR + p0];
        Vr[e][0] = *(__half2*)&u.x;
        Vr[e][1] = *(__half2*)&u.y;
    }

    __shared__ __half2 hs[BATCH * REC];
    __shared__ float   rs[BATCH];

    for (int si = 0; si < S_PER_CTA; si++) {
        int s = blockIdx.y * S_PER_CTA + si;
        if (tid < 128) ((uint4*)hs)[tid] = ((const uint4*)&g_hh[s * (BATCH*REC)])[tid];
        if (tid < BATCH) rs[tid] = 0.f;
        __syncthreads();

#pragma unroll 4
        for (int b = 0; b < BATCH; b++) {
            __half2 hv[REC];
            *(uint4*)&hv[0]  = *(const uint4*)&hs[b * REC];
            *(uint4*)&hv[4]  = *(const uint4*)&hs[b * REC + 4];
            *(uint4*)&hv[8]  = *(const uint4*)&hs[b * REC + 8];
            *(uint4*)&hv[12] = *(const uint4*)&hs[b * REC + 12];
            __half2 z = __float2half2_rn(0.f);
            __half2 aE0 = z, aE1 = z, aO0 = z, aO1 = z;
#pragma unroll
            for (int e = 0; e < REC; e += 2) {
                aE0 = __hfma2(Vr[e][0],   hv[e],   aE0);
                aE1 = __hfma2(Vr[e][1],   hv[e],   aE1);
                aO0 = __hfma2(Vr[e+1][0], hv[e+1], aO0);
                aO1 = __hfma2(Vr[e+1][1], hv[e+1], aO1);
            }
            float2 f0 = __half22float2(__hadd2(aE0, aO0));
            float2 f1 = __half22float2(__hadd2(aE1, aO1));
            float p = (ex2f(f0.x) + ex2f(f0.y)) + (ex2f(f1.x) + ex2f(f1.y));
#pragma unroll
            for (int o = 16; o > 0; o >>= 1) p += __shfl_xor_sync(0xffffffffu, p, o);
            if ((tid & 31) == 0) atomicAdd(&rs[b], p);
        }
        __syncthreads();
        if (tid < BATCH) atomicAdd(&g_sums[s * BATCH + tid], rs[tid]);
        __syncthreads();
    }
}

__global__ void k_lse() {
    int i = blockIdx.x * blockDim.x + threadIdx.x;
    g_m[i] = log2f(g_sums[i]) * LN2;
}

__global__ void __launch_bounds__(TP) k_pass2(float* __restrict__ out) {
    int tid = threadIdx.x;
    int p0 = (blockIdx.x * VCH) / 2 + 2 * tid;
    int vbase = blockIdx.x * VCH + 4 * tid;

    __half2 Vr[REC][2];
#pragma unroll
    for (int e = 0; e < REC; e++) {
        uint2 u = *(const uint2*)&g_Vh[e * NPAIR + p0];
        Vr[e][0] = *(__half2*)&u.x;
        Vr[e][1] = *(__half2*)&u.y;
    }

    __shared__ __half2 hs[BATCH * REC];
    __shared__ float   ms[BATCH];

    for (int si = 0; si < S_PER_CTA; si++) {
        int s = blockIdx.y * S_PER_CTA + si;
        if (tid < 128) ((uint4*)hs)[tid] = ((const uint4*)&g_hh[s * (BATCH*REC)])[tid];
        if (tid < BATCH) ms[tid] = g_m[s * BATCH + tid];
        __syncthreads();

#pragma unroll 4
        for (int b = 0; b < BATCH; b++) {
            __half2 hv[REC];
            *(uint4*)&hv[0]  = *(const uint4*)&hs[b * REC];
            *(uint4*)&hv[4]  = *(const uint4*)&hs[b * REC + 4];
            *(uint4*)&hv[8]  = *(const uint4*)&hs[b * REC + 8];
            *(uint4*)&hv[12] = *(const uint4*)&hs[b * REC + 12];
            __half2 z = __float2half2_rn(0.f);
            __half2 aE0 = z, aE1 = z, aO0 = z, aO1 = z;
#pragma unroll
            for (int e = 0; e < REC; e += 2) {
                aE0 = __hfma2(Vr[e][0],   hv[e],   aE0);
                aE1 = __hfma2(Vr[e][1],   hv[e],   aE1);
                aO0 = __hfma2(Vr[e+1][0], hv[e+1], aO0);
                aO1 = __hfma2(Vr[e+1][1], hv[e+1], aO1);
            }
            float2 f0 = __half22float2(__hadd2(aE0, aO0));
            float2 f1 = __half22float2(__hadd2(aE1, aO1));
            float m = ms[b];
            float4 r;
            r.x = fmaf(f0.x, LN2, -m); r.y = fmaf(f0.y, LN2, -m);
            r.z = fmaf(f1.x, LN2, -m); r.w = fmaf(f1.y, LN2, -m);
            *(float4*)(out + (size_t)(s * BATCH + b) * VOCAB + vbase) = r;
        }
        __syncthreads();
    }
}

extern "C" void kernel_launch(void* const* d_in, const int* in_sizes, int n_in,
                              void* d_out, int out_size) {
    const int*   input_batch = (const int*)  d_in[0];
    const float* embedding   = (const float*)d_in[1];
    const float* U           = (const float*)d_in[2];
    const float* W           = (const float*)d_in[3];
    const float* V           = (const float*)d_in[4];
    const float* b1          = (const float*)d_in[5];
    const float* b2          = (const float*)d_in[6];
    const float* h0          = (const float*)d_in[7];
    float* out = (float*)d_out;

    k_zero  <<<NROWS / 256, 256>>>();
    k_transV<<<NPAIR / 125, 125>>>(V);
    k_ih    <<<(NROWS * REC) / 256, 256>>>(input_batch, embedding, U, b1, b2);
    k_rnn   <<<BATCH, 32>>>(W, h0);
    k_pass1 <<<dim3(VOCAB / VCH, SEQ / S_PER_CTA), TP>>>();
    k_lse   <<<NROWS / 256, 256>>>();
    k_pass2 <<<dim3(VOCAB / VCH, SEQ / S_PER_CTA), TP>>>(out);
}

// round 11
// speedup vs baseline: 2.2132x; 1.4455x over previous
#include <cuda_runtime.h>
#include <cuda_fp16.h>
#include <math.h>
#include <stdint.h>

#define VOCAB 32000
#define EMB 32
#define REC 16
#define SEQ 256
#define BATCH 32
#define NROWS (SEQ*BATCH)      // 8192
#define LOG2E 1.4426950408889634f
#define LN2   0.6931471805599453f

#define MCH 512                // rows per CTA chunk
#define NT 32                  // m-tiles per CTA (MCH/16)
#define GY (NROWS/MCH)         // 16
#define GX (VOCAB/128)         // 250 (8 warps * 16 vocab)
#define ASTRIDE 48             // bytes per smem A row (16 halves + 8 pad)

// ---- scratch ----
__device__ __half g_h16[NROWS*REC];     // hidden fp16, [row][e]
__device__ __half g_V16[VOCAB*REC];     // V*log2e fp16, [v][e]
__device__ float  g_ih[BATCH*SEQ*REC];
__device__ float  g_sums[NROWS];
__device__ float  g_m[NROWS];           // lse (nat)

// ---- helpers ----
__device__ __forceinline__ uint32_t su32(const void* p) {
    uint32_t a;
    asm("{ .reg .u64 t; cvta.to.shared.u64 t, %1; cvt.u32.u64 %0, t; }" : "=r"(a) : "l"(p));
    return a;
}
__device__ __forceinline__ float ex2f(float x) {
    float y; asm("ex2.approx.f32 %0, %1;" : "=f"(y) : "f"(x)); return y;
}
__device__ __forceinline__ float rcpf(float x) {
    float y; asm("rcp.approx.f32 %0, %1;" : "=f"(y) : "f"(x)); return y;
}
__device__ __forceinline__ void ldsmx4(uint32_t a[4], uint32_t addr) {
    asm volatile("ldmatrix.sync.aligned.m8n8.x4.shared.b16 {%0,%1,%2,%3}, [%4];"
        : "=r"(a[0]), "=r"(a[1]), "=r"(a[2]), "=r"(a[3]) : "r"(addr));
}
__device__ __forceinline__ void mma16(float c[4], const uint32_t a[4], uint32_t b0, uint32_t b1) {
    asm volatile("mma.sync.aligned.m16n8k16.row.col.f32.f16.f16.f32 "
        "{%0,%1,%2,%3},{%4,%5,%6,%7},{%8,%9},{%0,%1,%2,%3};"
        : "+f"(c[0]), "+f"(c[1]), "+f"(c[2]), "+f"(c[3])
        : "r"(a[0]), "r"(a[1]), "r"(a[2]), "r"(a[3]), "r"(b0), "r"(b1));
}

// ---- small kernels ----
__global__ void k_zero() { g_sums[blockIdx.x * blockDim.x + threadIdx.x] = 0.f; }

__global__ void k_prepV(const float* __restrict__ V) {
    int v = blockIdx.x * 128 + threadIdx.x;
    const float4* s = (const float4*)(V + (size_t)v * REC);
    __half2 o[8];
#pragma unroll
    for (int q = 0; q < 4; q++) {
        float4 f = s[q];
        o[2*q]   = __floats2half2_rn(f.x * LOG2E, f.y * LOG2E);
        o[2*q+1] = __floats2half2_rn(f.z * LOG2E, f.w * LOG2E);
    }
    uint4* d = (uint4*)g_V16 + (size_t)v * 2;
    d[0] = *(uint4*)&o[0];
    d[1] = *(uint4*)&o[4];
}

__global__ void k_ih(const int* __restrict__ idx, const float* __restrict__ emb,
                     const float* __restrict__ U, const float* __restrict__ b1,
                     const float* __restrict__ b2) {
    int i = blockIdx.x * blockDim.x + threadIdx.x;
    int row = i >> 4, j = i & 15;
    int t = row >> 5, b = row & 31;
    int tok = idx[row];
    const float4* x4 = (const float4*)(emb + (size_t)tok * EMB);
    const float4* u4 = (const float4*)(U + j * EMB);
    float acc = b1[j] + b2[j];
#pragma unroll
    for (int q = 0; q < 8; q++) {
        float4 x = x4[q], u = u4[q];
        acc = fmaf(x.x, u.x, acc); acc = fmaf(x.y, u.y, acc);
        acc = fmaf(x.z, u.z, acc); acc = fmaf(x.w, u.w, acc);
    }
    g_ih[b * (SEQ * REC) + t * REC + j] = acc * (2.0f * LOG2E);
}

__global__ void k_rnn(const float* __restrict__ W, const float* __restrict__ h0) {
    __shared__ float ihs[SEQ * REC];
    __shared__ float hsm[2][REC];
    int b = blockIdx.x, lane = threadIdx.x;

#pragma unroll 8
    for (int i = lane; i < SEQ * REC; i += 32)
        ihs[i] = g_ih[b * (SEQ * REC) + i];

    int j = lane >> 1, half = lane & 1;
    float Wr[8];
#pragma unroll
    for (int k = 0; k < 8; k++) Wr[k] = W[j * REC + half * 8 + k];

    if (lane < REC) hsm[0][lane] = h0[lane];
    __syncwarp();

    int cur = 0;
    __half* hrow = &g_h16[b * REC];
    for (int t = 0; t < SEQ; t++) {
        if (!half) hrow[j] = __float2half_rn(hsm[cur][j]);
        if (t == SEQ - 1) break;
        hrow += BATCH * REC;

        const float* hp = &hsm[cur][half * 8];
        float a0 = Wr[0]*hp[0], a1 = Wr[1]*hp[1];
        a0 = fmaf(Wr[2], hp[2], a0); a1 = fmaf(Wr[3], hp[3], a1);
        a0 = fmaf(Wr[4], hp[4], a0); a1 = fmaf(Wr[5], hp[5], a1);
        a0 = fmaf(Wr[6], hp[6], a0); a1 = fmaf(Wr[7], hp[7], a1);
        float acc = a0 + a1;
        acc += __shfl_xor_sync(0xffffffffu, acc, 1);
        float z = fmaf(acc, 2.0f * LOG2E, ihs[t * REC + j]);
        float e = ex2f(z);
        float hn = fmaf(-2.0f, rcpf(1.0f + e), 1.0f);
        if (!half) hsm[cur ^ 1][j] = hn;
        __syncwarp();
        cur ^= 1;
    }
}

__global__ void k_lse() {
    int i = blockIdx.x * blockDim.x + threadIdx.x;
    g_m[i] = log2f(g_sums[i]) * LN2;
}

// ---- HMMA pass kernels: 256 thr, warp = 16-vocab strip, CTA = 128 vocab x 512 rows ----
// B col perm: tile0 cols -> vocab {0,1,4,5,8,9,12,13}, tile1 -> +2 (so each thread's
// 4 accumulators are 4 consecutive vocab -> STG.128 epilogue / simple sums).
__device__ __forceinline__ void load_bfrag(uint32_t B[2][2], int w0, int lane) {
    int n = lane >> 2, q = lane & 3;
#pragma unroll
    for (int t = 0; t < 2; t++) {
        int v = w0 + (n >> 1) * 4 + (n & 1) + t * 2;
        const uint32_t* vp = (const uint32_t*)&g_V16[(size_t)v * REC];
        B[t][0] = vp[q];        // e = 2q, 2q+1
        B[t][1] = vp[q + 4];    // e = 2q+8, 2q+9
    }
}

__global__ void __launch_bounds__(256) k_p1() {
    __shared__ __align__(16) char smA[MCH * ASTRIDE];
    __shared__ float ssum[MCH];
    int tid = threadIdx.x, wid = tid >> 5, lane = tid & 31;
    int mbase = blockIdx.y * MCH;
    int w0 = blockIdx.x * 128 + wid * 16;

    // stage A rows (16 halves -> 48B-stride rows)
    for (int r = tid; r < MCH; r += 256) {
        const uint4* s = (const uint4*)&g_h16[(size_t)(mbase + r) * REC];
        uint4 x0 = s[0], x1 = s[1];
        *(uint4*)(smA + r * ASTRIDE)      = x0;
        *(uint4*)(smA + r * ASTRIDE + 16) = x1;
    }
    for (int r = tid; r < MCH; r += 256) ssum[r] = 0.f;

    uint32_t B[2][2];
    load_bfrag(B, w0, lane);

    uint32_t abase = su32(smA) + (lane & 15) * ASTRIDE + (lane >> 4) * 16;
    __syncthreads();

    int q = lane & 3, g = lane >> 2;
    for (int i = 0; i < NT; i++) {
        int mt = (i + wid * 4) & (NT - 1);
        uint32_t a[4];
        ldsmx4(a, abase + mt * (16 * ASTRIDE));
        float c[4] = {0,0,0,0}, d[4] = {0,0,0,0};
        mma16(c, a, B[0][0], B[0][1]);
        mma16(d, a, B[1][0], B[1][1]);
        float lo = (ex2f(c[0]) + ex2f(c[1])) + (ex2f(d[0]) + ex2f(d[1]));
        float hi = (ex2f(c[2]) + ex2f(c[3])) + (ex2f(d[2]) + ex2f(d[3]));
        lo += __shfl_xor_sync(0xffffffffu, lo, 1);
        lo += __shfl_xor_sync(0xffffffffu, lo, 2);
        hi += __shfl_xor_sync(0xffffffffu, hi, 1);
        hi += __shfl_xor_sync(0xffffffffu, hi, 2);
        if (q == 0) {
            atomicAdd(&ssum[mt * 16 + g], lo);
            atomicAdd(&ssum[mt * 16 + g + 8], hi);
        }
    }
    __syncthreads();
    for (int r = tid; r < MCH; r += 256) atomicAdd(&g_sums[mbase + r], ssum[r]);
}

__global__ void __launch_bounds__(256) k_p2(float* __restrict__ out) {
    __shared__ __align__(16) char smA[MCH * ASTRIDE];
    __shared__ float ms[MCH];
    int tid = threadIdx.x, wid = tid >> 5, lane = tid & 31;
    int mbase = blockIdx.y * MCH;
    int w0 = blockIdx.x * 128 + wid * 16;

    for (int r = tid; r < MCH; r += 256) {
        const uint4* s = (const uint4*)&g_h16[(size_t)(mbase + r) * REC];
        uint4 x0 = s[0], x1 = s[1];
        *(uint4*)(smA + r * ASTRIDE)      = x0;
        *(uint4*)(smA + r * ASTRIDE + 16) = x1;
    }
    for (int r = tid; r < MCH; r += 256) ms[r] = g_m[mbase + r];

    uint32_t B[2][2];
    load_bfrag(B, w0, lane);

    uint32_t abase = su32(smA) + (lane & 15) * ASTRIDE + (lane >> 4) * 16;
    __syncthreads();

    int q = lane & 3, g = lane >> 2;
    int vcol = w0 + 4 * q;
    for (int i = 0; i < NT; i++) {
        int mt = (i + wid * 4) & (NT - 1);
        uint32_t a[4];
        ldsmx4(a, abase + mt * (16 * ASTRIDE));
        float c[4] = {0,0,0,0}, d[4] = {0,0,0,0};
        mma16(c, a, B[0][0], B[0][1]);
        mma16(d, a, B[1][0], B[1][1]);
        int r0 = mt * 16 + g;
        float m0 = ms[r0], m1 = ms[r0 + 8];
        float4 o0, o1;
        o0.x = fmaf(c[0], LN2, -m0); o0.y = fmaf(c[1], LN2, -m0);
        o0.z = fmaf(d[0], LN2, -m0); o0.w = fmaf(d[1], LN2, -m0);
        o1.x = fmaf(c[2], LN2, -m1); o1.y = fmaf(c[3], LN2, -m1);
        o1.z = fmaf(d[2], LN2, -m1); o1.w = fmaf(d[3], LN2, -m1);
        *(float4*)(out + (size_t)(mbase + r0) * VOCAB + vcol)     = o0;
        *(float4*)(out + (size_t)(mbase + r0 + 8) * VOCAB + vcol) = o1;
    }
}

extern "C" void kernel_launch(void* const* d_in, const int* in_sizes, int n_in,
                              void* d_out, int out_size) {
    const int*   input_batch = (const int*)  d_in[0];
    const float* embedding   = (const float*)d_in[1];
    const float* U           = (const float*)d_in[2];
    const float* W           = (const float*)d_in[3];
    const float* V           = (const float*)d_in[4];
    const float* b1          = (const float*)d_in[5];
    const float* b2          = (const float*)d_in[6];
    const float* h0          = (const float*)d_in[7];
    float* out = (float*)d_out;

    k_zero <<<NROWS / 256, 256>>>();
    k_prepV<<<VOCAB / 128, 128>>>(V);
    k_ih   <<<(NROWS * REC) / 256, 256>>>(input_batch, embedding, U, b1, b2);
    k_rnn  <<<BATCH, 32>>>(W, h0);
    k_p1   <<<dim3(GX, GY), 256>>>();
    k_lse  <<<NROWS / 256, 256>>>();
    k_p2   <<<dim3(GX, GY), 256>>>(out);
}